// round 13
// baseline (speedup 1.0000x reference)
#include <cuda_runtime.h>
#include <math_constants.h>

// Problem constants (fixed by the dataset)
#define B_      128
#define L_I     2
#define L_Q     10
#define N_ACT   8
#define IM      64
#define IMP     66
#define NPIX    4096
#define NTHR    1024

#define ISTR    72           // in_s row stride; data rows 1..64, cols 4..67; halos r0/65, c3/68
#define IROWS   66
#define RSTR    68           // r_s row stride; data rows 1..64, cols 1..64; zero halo ring

// smem float-offsets (dynamic region)
#define F_QR      0          // qr: 10*4096 = 40960 floats (slow path)
#define F_INS     0          // in_s[2][66][72] = 9504 floats (alias)
#define STG_HW    9504       // 2700 (alias)
#define STG_RW    12204      // 150 (alias)
#define STG_HB    12354      // 150 (alias)
#define F_RS      40960      // r_s 66*68 = 4488
#define F_VS      45448      // v_s 66*66 = 4356 (slow path only)
#define F_QW      49804      // 90
#define F_WW      49894      // 90
#define F_FC      49984      // 80
#define SMEM_FLTS 50064
#define SMEM_TOT  (SMEM_FLTS * 4)

#define Q_ELEMS   (B_ * L_Q * NPIX)       // 5242880
#define LOGIT_OFF Q_ELEMS
#define ACT_OFF   (Q_ELEMS + B_ * N_ACT)  // 5243904

// grid-wide argmax state (self-resetting each launch -> graph-replay safe)
__device__ unsigned long long g_best  = 0ULL;
__device__ unsigned int       g_count = 0u;

__device__ __forceinline__ unsigned int ordered_f32(float f) {
    unsigned int u = __float_as_uint(f);
    return (u & 0x80000000u) ? ~u : (u | 0x80000000u);
}

// logits from qv[10], write to out, contribute to grid argmax. One thread calls.
__device__ __forceinline__ void logits_and_argmax(const float* qv, const float* fc_s,
                                                  float* out, int b) {
    float best = -CUDART_INF_F;
    int   bi   = 0;
    #pragma unroll
    for (int a = 0; a < N_ACT; a++) {
        float s = 0.f;
        #pragma unroll
        for (int o = 0; o < L_Q; o++) s += fc_s[a * L_Q + o] * qv[o];
        out[LOGIT_OFF + b * N_ACT + a] = s;
        if (s > best) { best = s; bi = b * N_ACT + a; }   // strict > keeps first
    }
    const unsigned long long key =
        ((unsigned long long)ordered_f32(best) << 32) |
        (unsigned long long)(0xFFFFFFFFu - (unsigned int)bi);
    atomicMax(&g_best, key);
    __threadfence();
    const unsigned int cnt = atomicAdd(&g_count, 1u);
    if (cnt == B_ - 1u) {
        const unsigned long long k2 = atomicMax(&g_best, 0ULL);   // atomic read
        const unsigned int flat = 0xFFFFFFFFu - (unsigned int)(k2 & 0xFFFFFFFFu);
        out[ACT_OFF] = (float)flat;
        g_best = 0ULL;
        __threadfence();
        atomicExch(&g_count, 0u);
    }
}

__global__ __launch_bounds__(NTHR, 1)
void vin_main_kernel(const float* __restrict__ in,
                     const int*   __restrict__ sx_,
                     const int*   __restrict__ sy_,
                     const int*   __restrict__ kptr,   // may be null
                     const float* __restrict__ h_w,
                     const float* __restrict__ h_b,
                     const float* __restrict__ r_w,
                     const float* __restrict__ q_w,
                     const float* __restrict__ w,
                     const float* __restrict__ fc_w,
                     float* __restrict__ out)
{
    extern __shared__ __align__(16) float sm[];
    float* qr   = sm + F_QR;      // slow path only
    float* in_s = sm + F_INS;     // [2][66][72] halo-padded (alias of qr)
    float* r_s  = sm + F_RS;      // [66][68], data rows/cols 1..64, zero halo ring
    float* v_s  = sm + F_VS;      // [66][66], slow path only
    float* qw_s = sm + F_QW;      // [90]
    float* ww_s = sm + F_WW;      // [90]
    float* fc_s = sm + F_FC;      // [80]
    __shared__ float weffb[20];   // [0..17]=weff, [18]=beff
    __shared__ float qout_s[10];  // slow-path gather (kept for symmetry)

    const int b   = blockIdx.x;
    const int tid = threadIdx.x;

    // ================ S0: stage everything (coalesced), zero halo rings =============
    {   // input: 2048 float4; data row r -> in_s row r+1, col base 4 (16B aligned)
        const float4* inb4 = (const float4*)(in + (size_t)b * L_I * NPIX);
        #pragma unroll
        for (int i = 0; i < 2; i++) {
            const int e   = tid + i * NTHR;           // 0..2047
            const int ch  = e >> 10;
            const int rem = e & 1023;
            const int row = rem >> 4, c4 = rem & 15;
            *(float4*)&in_s[ch * (IROWS * ISTR) + (row + 1) * ISTR + 4 + 4 * c4] =
                inb4[ch * 1024 + row * 16 + c4];
        }
    }
    {   // h_w: 675 float4, coalesced, single round
        const float4* hw4 = (const float4*)h_w;
        float4* dst = (float4*)(sm + STG_HW);
        if (tid < 675) dst[tid] = hw4[tid];
    }
    if (tid < 150) { sm[STG_RW + tid] = r_w[tid]; sm[STG_HB + tid] = h_b[tid]; }
    if (tid < 90)  { qw_s[tid] = q_w[tid]; ww_s[tid] = w[tid]; }
    if (tid < 80)  fc_s[tid] = fc_w[tid];
    // in_s halos: rows 0 & 65 (cols 3..68, 66 each) and cols 3 & 68 (rows 1..64), 2 ch
    if (tid < 264) {            // top/bottom rows: 2ch * 2rows * 66cols
        const int ch = tid / 132, rem = tid % 132;
        const int r2 = (rem < 66) ? 0 : 65, c = 3 + (rem % 66);
        in_s[ch * (IROWS * ISTR) + r2 * ISTR + c] = 0.f;
    } else if (tid < 520) {     // side cols: 2ch * 64rows * 2cols
        const int idx = tid - 264;            // 0..255
        const int ch = idx >> 7, rem = idx & 127;
        const int row = 1 + (rem >> 1), c = (rem & 1) ? 68 : 3;
        in_s[ch * (IROWS * ISTR) + row * ISTR + c] = 0.f;
    } else if (tid < 652) {     // r_s halo rows 0 & 65 (cols 0..65): 132 cells
        const int idx = tid - 520;
        const int r2 = (idx < 66) ? 0 : 65, c = idx % 66;
        r_s[r2 * RSTR + c] = 0.f;
    } else if (tid < 780) {     // r_s halo cols 0 & 65 (rows 1..64): 128 cells
        const int idx = tid - 652;
        const int row = 1 + (idx >> 1), c = (idx & 1) * 65;
        r_s[row * RSTR + c] = 0.f;
    }
    __syncthreads();   // sync1

    // ================ S1: weight collapse from smem (16 lanes per item) =============
    {
        const int item = tid >> 4;        // 0..63 (only 0..18 meaningful)
        const int l    = tid & 15;
        float acc = 0.f;
        if (item < 18) {
            #pragma unroll
            for (int s = 0; s < 10; s++) {
                const int c = l + 16 * s;
                if (c < 150) acc += sm[STG_RW + c] * sm[STG_HW + 18 * c + item];
            }
        } else if (item == 18) {
            #pragma unroll
            for (int s = 0; s < 10; s++) {
                const int c = l + 16 * s;
                if (c < 150) acc += sm[STG_RW + c] * sm[STG_HB + c];
            }
        }
        acc += __shfl_xor_sync(0xFFFFFFFFu, acc, 8);
        acc += __shfl_xor_sync(0xFFFFFFFFu, acc, 4);
        acc += __shfl_xor_sync(0xFFFFFFFFu, acc, 2);
        acc += __shfl_xor_sync(0xFFFFFFFFu, acc, 1);
        if (l == 0 && item < 19) weffb[item] = acc;
    }
    const int nz = (tid < 90) ? (ww_s[tid] != 0.f) : 0;
    const int f  = __syncthreads_or(nz);   // sync2: weffb ready, flag uniform

    // ================ S2: r-conv, 4-pixel quad, unconditional scalar LDS ============
    {
        const int x  = tid >> 4;           // output row 0..63
        const int y0 = (tid & 15) * 4;     // 0,4,...,60
        float wr[18];
        #pragma unroll
        for (int j = 0; j < 18; j++) wr[j] = weffb[j];
        float a0 = weffb[18], a1 = a0, a2 = a0, a3 = a0;
        #pragma unroll
        for (int ci = 0; ci < L_I; ci++) {
            #pragma unroll
            for (int kh = 0; kh < 3; kh++) {
                // input rows x-1..x+1 -> in_s rows x..x+2; data col y -> in_s col y+4
                const float* rp = &in_s[ci * (IROWS * ISTR) + (x + kh) * ISTR + y0 + 3];
                const float w0 = rp[0], w1 = rp[1], w2 = rp[2];
                const float w3 = rp[3], w4 = rp[4], w5 = rp[5];
                const float c0 = wr[ci * 9 + kh * 3 + 0];
                const float c1 = wr[ci * 9 + kh * 3 + 1];
                const float c2 = wr[ci * 9 + kh * 3 + 2];
                a0 += w0 * c0 + w1 * c1 + w2 * c2;
                a1 += w1 * c0 + w2 * c1 + w3 * c2;
                a2 += w2 * c0 + w3 * c1 + w4 * c2;
                a3 += w3 * c0 + w4 * c1 + w5 * c2;
            }
        }
        float* rp = &r_s[(x + 1) * RSTR + y0 + 1];
        rp[0] = a0; rp[1] = a1; rp[2] = a2; rp[3] = a3;
    }
    __syncthreads();   // sync3: r_s ready

    float* outb = out + (size_t)b * L_Q * NPIX;

    if (!f) {
        // ============ FAST PATH (R9-identical shape): q == conv(r, q_w) =============
        const int row = tid >> 4;            // 0..63
        const int y0  = (tid & 15) * 4;      // 0,4,...,60
        // window: r_s rows row..row+2 (halo ok), cols y0..y0+5 (data cols y0-1..y0+4)
        float wnd[3][6];
        #pragma unroll
        for (int kh = 0; kh < 3; kh++) {
            #pragma unroll
            for (int m = 0; m < 3; m++) {
                const float2 v = *(const float2*)&r_s[(row + kh) * RSTR + y0 + 2 * m];
                wnd[kh][2 * m]     = v.x;
                wnd[kh][2 * m + 1] = v.y;
            }
        }
        float* obase = outb + row * IM + y0;
        #pragma unroll
        for (int chk = 0; chk < 5; chk++) {      // 2 output channels per chunk
            float qa[18];
            #pragma unroll
            for (int j = 0; j < 18; j++) qa[j] = qw_s[chk * 18 + j];
            float a0[4], a1[4];
            #pragma unroll
            for (int px = 0; px < 4; px++) {
                float s0 = 0.f, s1 = 0.f;
                #pragma unroll
                for (int kh = 0; kh < 3; kh++)
                    #pragma unroll
                    for (int kw = 0; kw < 3; kw++) {
                        const float t = wnd[kh][px + kw];
                        s0 += t * qa[kh * 3 + kw];
                        s1 += t * qa[9 + kh * 3 + kw];
                    }
                a0[px] = s0; a1[px] = s1;
            }
            *(float4*)(obase + (2 * chk)     * NPIX) = make_float4(a0[0], a0[1], a0[2], a0[3]);
            *(float4*)(obase + (2 * chk + 1) * NPIX) = make_float4(a1[0], a1[1], a1[2], a1[3]);
        }
        // gather + logits + argmax (one thread per image)
        if (tid == 0) {
            const int sx = sx_[b], sy = sy_[b];
            float qv[L_Q];
            #pragma unroll
            for (int oc = 0; oc < L_Q; oc++) {
                float a = 0.f;
                #pragma unroll
                for (int kh = 0; kh < 3; kh++)
                    #pragma unroll
                    for (int kw = 0; kw < 3; kw++)
                        a += r_s[(sx + kh) * RSTR + sy + kw] * qw_s[oc * 9 + kh * 3 + kw];
                qv[oc] = a;
            }
            logits_and_argmax(qv, fc_s, out, b);
        }
        return;
    }

    // ================ SLOW PATH: w != 0, full k-iteration loop =======================
    {
        for (int i = tid; i < IMP * IMP; i += NTHR) v_s[i] = 0.f;
        __syncthreads();

        // qr[o] = conv(r, q_w[o]); v0 = max_o
        #pragma unroll
        for (int c = 0; c < 4; c++) {
            const int p = tid + c * NTHR;
            const int x = p >> 6, y = p & 63;
            float t[9];
            for (int kh = 0; kh < 3; kh++)
                for (int kw = 0; kw < 3; kw++)
                    t[kh * 3 + kw] = r_s[(x + kh) * RSTR + y + kw];
            float vmax = -CUDART_INF_F;
            for (int oc = 0; oc < L_Q; oc++) {
                float a = 0.f;
                for (int j = 0; j < 9; j++) a += t[j] * qw_s[oc * 9 + j];
                qr[oc * NPIX + p] = a;
                vmax = fmaxf(vmax, a);
            }
            v_s[(x + 1) * IMP + y + 1] = vmax;
        }
        __syncthreads();

        const int kk = (kptr != nullptr) ? *kptr : 40;
        for (int it = 0; it < kk - 1; it++) {
            float nv[4];
            #pragma unroll
            for (int c = 0; c < 4; c++) {
                const int p = tid + c * NTHR;
                const int x = p >> 6, y = p & 63;
                float t[9];
                for (int kh = 0; kh < 3; kh++)
                    for (int kw = 0; kw < 3; kw++)
                        t[kh * 3 + kw] = v_s[(x + kh) * IMP + y + kw];
                float vmax = -CUDART_INF_F;
                for (int oc = 0; oc < L_Q; oc++) {
                    float a = qr[oc * NPIX + p];
                    for (int j = 0; j < 9; j++) a += t[j] * ww_s[oc * 9 + j];
                    vmax = fmaxf(vmax, a);
                }
                nv[c] = vmax;
            }
            __syncthreads();
            #pragma unroll
            for (int c = 0; c < 4; c++) {
                const int p = tid + c * NTHR;
                const int x = p >> 6, y = p & 63;
                v_s[(x + 1) * IMP + y + 1] = nv[c];
            }
            __syncthreads();
        }

        // final q = qr + conv(v, w) -> gmem
        #pragma unroll
        for (int c = 0; c < 4; c++) {
            const int p = tid + c * NTHR;
            const int x = p >> 6, y = p & 63;
            float t[9];
            for (int kh = 0; kh < 3; kh++)
                for (int kw = 0; kw < 3; kw++)
                    t[kh * 3 + kw] = v_s[(x + kh) * IMP + y + kw];
            for (int oc = 0; oc < L_Q; oc++) {
                float a = qr[oc * NPIX + p];
                for (int j = 0; j < 9; j++) a += t[j] * ww_s[oc * 9 + j];
                outb[oc * NPIX + p] = a;
            }
        }
        __syncthreads();

        if (tid == 0) {
            const int sx = sx_[b], sy = sy_[b];
            float qv[L_Q];
            for (int oc = 0; oc < L_Q; oc++) {
                float a = qr[oc * NPIX + sx * IM + sy];
                for (int kh = 0; kh < 3; kh++)
                    for (int kw = 0; kw < 3; kw++)
                        a += v_s[(sx + kh) * IMP + sy + kw] * ww_s[oc * 9 + kh * 3 + kw];
                qv[oc] = a;
            }
            logits_and_argmax(qv, fc_s, out, b);
        }
        (void)qout_s;
    }
}

extern "C" void kernel_launch(void* const* d_in, const int* in_sizes, int n_in,
                              void* d_out, int out_size)
{
    // Inputs: input_view, state_x, state_y, [k], h_w, h_b, r_w, q_w, w, fc_w
    int hw_idx = -1;
    for (int i = 0; i < n_in; i++) {
        if (in_sizes[i] == 2700) { hw_idx = i; break; }
    }
    if (hw_idx < 0) hw_idx = 4;

    const float* in_v = (const float*)d_in[0];
    const int*   sx   = (const int*)d_in[1];
    const int*   sy   = (const int*)d_in[2];
    const int*   kptr = (hw_idx == 4) ? (const int*)d_in[3] : nullptr;
    const float* h_w  = (const float*)d_in[hw_idx];
    const float* h_b  = (const float*)d_in[hw_idx + 1];
    const float* r_w  = (const float*)d_in[hw_idx + 2];
    const float* q_w  = (const float*)d_in[hw_idx + 3];
    const float* w    = (const float*)d_in[hw_idx + 4];
    const float* fc_w = (const float*)d_in[hw_idx + 5];
    float* out = (float*)d_out;

    cudaFuncSetAttribute(vin_main_kernel,
                         cudaFuncAttributeMaxDynamicSharedMemorySize, SMEM_TOT);

    vin_main_kernel<<<B_, NTHR, SMEM_TOT>>>(in_v, sx, sy, kptr, h_w, h_b, r_w,
                                            q_w, w, fc_w, out);
}

// round 14
// speedup vs baseline: 1.4630x; 1.4630x over previous
#include <cuda_runtime.h>
#include <math_constants.h>

// Problem constants (fixed by the dataset)
#define B_      128
#define L_I     2
#define L_Q     10
#define N_ACT   8
#define IM      64
#define IMP     66
#define NPIX    4096
#define NTHR    1024
#define PPT     4            // pixels per thread = 4096/1024

#define ISTR    72           // in_s row stride; data rows 1..64 cols 4..67; halos r0/65, c3/68
#define IROWS   66

// smem float-offsets (dynamic region)
#define F_QR      0          // qr: 10*4096 = 40960 floats (slow path)
#define F_INS     0          // in_s[2][66][72] = 9504 floats (alias of qr)
#define STG_HW    9504       // 2700 (alias)
#define STG_RW    12204      // 150 (alias)
#define STG_HB    12354      // 150 (alias)
#define F_RS      40960      // r_s [66][66] = 4356, data rows/cols 1..64, zero halo ring
#define F_VS      45316      // v_s [66][66] = 4356 (slow path only)
#define F_QW      49672      // 90
#define F_WW      49762      // 90
#define F_FC      49852      // 80
#define F_QOUT    49932      // 10
#define F_LARR    49942      // 8
#define SMEM_FLTS 49950
#define SMEM_TOT  (SMEM_FLTS * 4)

#define Q_ELEMS   (B_ * L_Q * NPIX)       // 5242880
#define LOGIT_OFF Q_ELEMS
#define ACT_OFF   (Q_ELEMS + B_ * N_ACT)  // 5243904

// grid-wide argmax state (self-resetting each launch -> graph-replay safe)
__device__ unsigned long long g_best  = 0ULL;
__device__ unsigned int       g_count = 0u;

__device__ __forceinline__ unsigned int ordered_f32(float f) {
    unsigned int u = __float_as_uint(f);
    return (u & 0x80000000u) ? ~u : (u | 0x80000000u);
}

__global__ __launch_bounds__(NTHR, 1)
void vin_main_kernel(const float* __restrict__ in,
                     const int*   __restrict__ sx_,
                     const int*   __restrict__ sy_,
                     const int*   __restrict__ kptr,   // may be null
                     const float* __restrict__ h_w,
                     const float* __restrict__ h_b,
                     const float* __restrict__ r_w,
                     const float* __restrict__ q_w,
                     const float* __restrict__ w,
                     const float* __restrict__ fc_w,
                     float* __restrict__ out)
{
    extern __shared__ __align__(16) float sm[];
    float* qr   = sm + F_QR;      // slow path only
    float* in_s = sm + F_INS;     // [2][66][72] halo-padded (alias of qr)
    float* r_s  = sm + F_RS;      // [66][66], data rows/cols 1..64, zero halo ring
    float* v_s  = sm + F_VS;      // [66][66], slow path only
    float* qw_s = sm + F_QW;      // [90]
    float* ww_s = sm + F_WW;      // [90]
    float* fc_s = sm + F_FC;      // [80]
    float* qout = sm + F_QOUT;    // [10]
    float* larr = sm + F_LARR;    // [8]
    __shared__ float weffb[20];   // [0..17]=weff, [18]=beff

    const int b   = blockIdx.x;
    const int tid = threadIdx.x;

    // ================ S0: stage everything (coalesced), zero halo rings =============
    {   // input: 2048 float4; data row r -> in_s row r+1, col base 4 (16B aligned)
        const float4* inb4 = (const float4*)(in + (size_t)b * L_I * NPIX);
        #pragma unroll
        for (int i = 0; i < 2; i++) {
            const int e   = tid + i * NTHR;           // 0..2047
            const int ch  = e >> 10;
            const int rem = e & 1023;
            const int row = rem >> 4, c4 = rem & 15;
            *(float4*)&in_s[ch * (IROWS * ISTR) + (row + 1) * ISTR + 4 + 4 * c4] =
                inb4[ch * 1024 + row * 16 + c4];
        }
    }
    {   // h_w: 675 float4, coalesced, single round
        const float4* hw4 = (const float4*)h_w;
        float4* dst = (float4*)(sm + STG_HW);
        if (tid < 675) dst[tid] = hw4[tid];
    }
    if (tid < 150) { sm[STG_RW + tid] = r_w[tid]; sm[STG_HB + tid] = h_b[tid]; }
    if (tid < 90)  { qw_s[tid] = q_w[tid]; ww_s[tid] = w[tid]; }
    if (tid < 80)  fc_s[tid] = fc_w[tid];
    // in_s halos: rows 0 & 65 (cols 3..68) and cols 3 & 68 (rows 1..64), both channels
    if (tid < 264) {            // top/bottom rows: 2ch * 2rows * 66cols
        const int ch = tid / 132, rem = tid % 132;
        const int r2 = (rem < 66) ? 0 : 65, c = 3 + (rem % 66);
        in_s[ch * (IROWS * ISTR) + r2 * ISTR + c] = 0.f;
    } else if (tid < 520) {     // side cols: 2ch * 64rows * 2cols
        const int idx = tid - 264;            // 0..255
        const int ch = idx >> 7, rem = idx & 127;
        const int row = 1 + (rem >> 1), c = (rem & 1) ? 68 : 3;
        in_s[ch * (IROWS * ISTR) + row * ISTR + c] = 0.f;
    } else if (tid < 652) {     // r_s halo rows 0 & 65 (cols 0..65)
        const int idx = tid - 520;
        const int r2 = (idx < 66) ? 0 : 65, c = idx % 66;
        r_s[r2 * IMP + c] = 0.f;
    } else if (tid < 780) {     // r_s halo cols 0 & 65 (rows 1..64)
        const int idx = tid - 652;
        const int row = 1 + (idx >> 1), c = (idx & 1) * 65;
        r_s[row * IMP + c] = 0.f;
    }
    __syncthreads();   // sync1

    // ================ S1: weight collapse from smem (16 lanes per item) =============
    // weff[i*9+t] = sum_c r_w[c] * h_w[18c + (i*9+t)];  beff = sum_c r_w[c]*h_b[c]
    {
        const int item = tid >> 4;        // 0..63 (only 0..18 meaningful)
        const int l    = tid & 15;
        float acc = 0.f;
        if (item < 18) {
            #pragma unroll
            for (int s = 0; s < 10; s++) {
                const int c = l + 16 * s;
                if (c < 150) acc += sm[STG_RW + c] * sm[STG_HW + 18 * c + item];
            }
        } else if (item == 18) {
            #pragma unroll
            for (int s = 0; s < 10; s++) {
                const int c = l + 16 * s;
                if (c < 150) acc += sm[STG_RW + c] * sm[STG_HB + c];
            }
        }
        acc += __shfl_xor_sync(0xFFFFFFFFu, acc, 8);
        acc += __shfl_xor_sync(0xFFFFFFFFu, acc, 4);
        acc += __shfl_xor_sync(0xFFFFFFFFu, acc, 2);
        acc += __shfl_xor_sync(0xFFFFFFFFu, acc, 1);
        if (l == 0 && item < 19) weffb[item] = acc;
    }
    const int nz = (tid < 90) ? (ww_s[tid] != 0.f) : 0;
    const int f  = __syncthreads_or(nz);   // sync2: weffb ready, flag uniform

    // ====== S2: r-conv, R9 pixel mapping (conflict-free), NO predication (padded) ===
    {
        float wr[18];
        #pragma unroll
        for (int j = 0; j < 18; j++) wr[j] = weffb[j];
        const float be = weffb[18];
        #pragma unroll
        for (int c = 0; c < PPT; c++) {
            const int p = tid + c * NTHR;
            const int x = p >> 6, y = p & 63;    // y consecutive within warp
            float acc = be;
            #pragma unroll
            for (int ci = 0; ci < L_I; ci++)
                #pragma unroll
                for (int kh = 0; kh < 3; kh++)
                    #pragma unroll
                    for (int kw = 0; kw < 3; kw++)
                        acc += in_s[ci * (IROWS * ISTR) + (x + kh) * ISTR + (y + kw + 3)]
                               * wr[ci * 9 + kh * 3 + kw];
            r_s[(x + 1) * IMP + (y + 1)] = acc;
        }
    }
    __syncthreads();   // sync3: r_s ready

    float* outb = out + (size_t)b * L_Q * NPIX;

    if (!f) {
        // ============ FAST PATH (verbatim R9): q == conv(r, q_w), scalar FFMA =======
        const int row = tid >> 4;            // 0..63
        const int y0  = (tid & 15) * 4;      // 0,4,...,60
        float wnd[3][6];
        #pragma unroll
        for (int kh = 0; kh < 3; kh++) {
            #pragma unroll
            for (int m = 0; m < 3; m++) {
                const float2 v = *(const float2*)&r_s[(row + kh) * IMP + y0 + 2 * m];
                wnd[kh][2 * m]     = v.x;
                wnd[kh][2 * m + 1] = v.y;
            }
        }
        float* obase = outb + row * IM + y0;
        #pragma unroll
        for (int chk = 0; chk < 5; chk++) {      // 2 output channels per chunk
            float qa[18];
            #pragma unroll
            for (int j = 0; j < 18; j++) qa[j] = qw_s[chk * 18 + j];
            float a0[4], a1[4];
            #pragma unroll
            for (int px = 0; px < 4; px++) {
                float s0 = 0.f, s1 = 0.f;
                #pragma unroll
                for (int kh = 0; kh < 3; kh++)
                    #pragma unroll
                    for (int kw = 0; kw < 3; kw++) {
                        const float t = wnd[kh][px + kw];
                        s0 += t * qa[kh * 3 + kw];
                        s1 += t * qa[9 + kh * 3 + kw];
                    }
                a0[px] = s0; a1[px] = s1;
            }
            *(float4*)(obase + (2 * chk)     * NPIX) = make_float4(a0[0], a0[1], a0[2], a0[3]);
            *(float4*)(obase + (2 * chk + 1) * NPIX) = make_float4(a1[0], a1[1], a1[2], a1[3]);
        }
        // gather q[b,:,sx,sy] from r_s (recompute, 10x9 FMA)
        {
            const int sx = sx_[b], sy = sy_[b];
            if (tid < L_Q) {
                float a = 0.f;
                #pragma unroll
                for (int kh = 0; kh < 3; kh++)
                    #pragma unroll
                    for (int kw = 0; kw < 3; kw++)
                        a += r_s[(sx + kh) * IMP + sy + kw] * qw_s[tid * 9 + kh * 3 + kw];
                qout[tid] = a;
            }
        }
        __syncthreads();
    } else {
        // ============ SLOW PATH: generic k-iteration loop (w != 0) ==================
        for (int i = tid; i < IMP * IMP; i += NTHR) v_s[i] = 0.f;
        __syncthreads();

        // qr[o] = conv(r, q_w[o]); v0 = max_o qr[o]
        #pragma unroll
        for (int c = 0; c < PPT; c++) {
            const int p = tid + c * NTHR;
            const int x = p >> 6, y = p & 63;
            float t[9];
            #pragma unroll
            for (int kh = 0; kh < 3; kh++)
                #pragma unroll
                for (int kw = 0; kw < 3; kw++)
                    t[kh * 3 + kw] = r_s[(x + kh) * IMP + (y + kw)];
            float vmax = -CUDART_INF_F;
            #pragma unroll
            for (int o = 0; o < L_Q; o++) {
                float a = 0.f;
                #pragma unroll
                for (int j = 0; j < 9; j++) a += t[j] * qw_s[o * 9 + j];
                qr[o * NPIX + p] = a;
                vmax = fmaxf(vmax, a);
            }
            v_s[(x + 1) * IMP + (y + 1)] = vmax;
        }
        __syncthreads();

        const int kk = (kptr != nullptr) ? *kptr : 40;
        for (int it = 0; it < kk - 1; it++) {
            float nv[PPT];
            #pragma unroll
            for (int c = 0; c < PPT; c++) {
                const int p = tid + c * NTHR;
                const int x = p >> 6, y = p & 63;
                float t[9];
                #pragma unroll
                for (int kh = 0; kh < 3; kh++)
                    #pragma unroll
                    for (int kw = 0; kw < 3; kw++)
                        t[kh * 3 + kw] = v_s[(x + kh) * IMP + (y + kw)];
                float vmax = -CUDART_INF_F;
                #pragma unroll
                for (int o = 0; o < L_Q; o++) {
                    float a = qr[o * NPIX + p];
                    #pragma unroll
                    for (int j = 0; j < 9; j++) a += t[j] * ww_s[o * 9 + j];
                    vmax = fmaxf(vmax, a);
                }
                nv[c] = vmax;
            }
            __syncthreads();
            #pragma unroll
            for (int c = 0; c < PPT; c++) {
                const int p = tid + c * NTHR;
                const int x = p >> 6, y = p & 63;
                v_s[(x + 1) * IMP + (y + 1)] = nv[c];
            }
            __syncthreads();
        }

        // final q = qr + conv(v, w) -> gmem
        #pragma unroll
        for (int c = 0; c < PPT; c++) {
            const int p = tid + c * NTHR;
            const int x = p >> 6, y = p & 63;
            float t[9];
            #pragma unroll
            for (int kh = 0; kh < 3; kh++)
                #pragma unroll
                for (int kw = 0; kw < 3; kw++)
                    t[kh * 3 + kw] = v_s[(x + kh) * IMP + (y + kw)];
            #pragma unroll
            for (int o = 0; o < L_Q; o++) {
                float a = qr[o * NPIX + p];
                #pragma unroll
                for (int j = 0; j < 9; j++) a += t[j] * ww_s[o * 9 + j];
                outb[o * NPIX + p] = a;
            }
        }
        // gather q[b,:,sx,sy]
        const int sx = sx_[b], sy = sy_[b];
        if (tid < L_Q) {
            float a = qr[tid * NPIX + sx * IM + sy];
            #pragma unroll
            for (int kh = 0; kh < 3; kh++)
                #pragma unroll
                for (int kw = 0; kw < 3; kw++)
                    a += v_s[(sx + kh) * IMP + sy + kw] * ww_s[tid * 9 + kh * 3 + kw];
            qout[tid] = a;
        }
        __syncthreads();
    }

    // ================ epilogue: logits + fused grid-wide argmax =====================
    if (tid < N_ACT) {
        float a = 0.f;
        #pragma unroll
        for (int o = 0; o < L_Q; o++) a += fc_s[tid * L_Q + o] * qout[o];
        out[LOGIT_OFF + b * N_ACT + tid] = a;
        larr[tid] = a;
    }
    __syncthreads();
    if (tid == 0) {
        float best = larr[0];
        int   bi   = b * N_ACT;
        #pragma unroll
        for (int a = 1; a < N_ACT; a++) {
            if (larr[a] > best) { best = larr[a]; bi = b * N_ACT + a; }
        }
        const unsigned long long key =
            ((unsigned long long)ordered_f32(best) << 32) |
            (unsigned long long)(0xFFFFFFFFu - (unsigned int)bi);
        atomicMax(&g_best, key);
        __threadfence();
        const unsigned int cnt = atomicAdd(&g_count, 1u);
        if (cnt == B_ - 1u) {
            const unsigned long long k2 = atomicMax(&g_best, 0ULL); // atomic read
            const unsigned int flat = 0xFFFFFFFFu - (unsigned int)(k2 & 0xFFFFFFFFu);
            out[ACT_OFF] = (float)flat;
            g_best = 0ULL;
            __threadfence();
            atomicExch(&g_count, 0u);
        }
    }
}

extern "C" void kernel_launch(void* const* d_in, const int* in_sizes, int n_in,
                              void* d_out, int out_size)
{
    // Inputs: input_view, state_x, state_y, [k], h_w, h_b, r_w, q_w, w, fc_w
    int hw_idx = -1;
    for (int i = 0; i < n_in; i++) {
        if (in_sizes[i] == 2700) { hw_idx = i; break; }
    }
    if (hw_idx < 0) hw_idx = 4;

    const float* in_v = (const float*)d_in[0];
    const int*   sx   = (const int*)d_in[1];
    const int*   sy   = (const int*)d_in[2];
    const int*   kptr = (hw_idx == 4) ? (const int*)d_in[3] : nullptr;
    const float* h_w  = (const float*)d_in[hw_idx];
    const float* h_b  = (const float*)d_in[hw_idx + 1];
    const float* r_w  = (const float*)d_in[hw_idx + 2];
    const float* q_w  = (const float*)d_in[hw_idx + 3];
    const float* w    = (const float*)d_in[hw_idx + 4];
    const float* fc_w = (const float*)d_in[hw_idx + 5];
    float* out = (float*)d_out;

    cudaFuncSetAttribute(vin_main_kernel,
                         cudaFuncAttributeMaxDynamicSharedMemorySize, SMEM_TOT);

    vin_main_kernel<<<B_, NTHR, SMEM_TOT>>>(in_v, sx, sy, kptr, h_w, h_b, r_w,
                                            q_w, w, fc_w, out);
}